// round 15
// baseline (speedup 1.0000x reference)
#include <cuda_runtime.h>
#include <cuda_fp16.h>
#include <math.h>
#include <stdint.h>

// ---------------------------------------------------------------------------
// Problem constants
// ---------------------------------------------------------------------------
#define NUM_E   8
#define TOPK    2
#define T_TOK   8192
#define NK      (T_TOK * TOPK)
#define HS      1024
#define FFN     4096
#define CAP     2048
#define KSPLIT  2                       // GEMM2 K-split factor

// ---------------------------------------------------------------------------
// Device scratch
// ---------------------------------------------------------------------------
__device__ int    g_flat_slot[NK];
__device__ int    g_slot_token[NUM_E * CAP];
__device__ __half g_xg[(size_t)NUM_E * CAP * HS];       // gathered x, fp16
__device__ __half g_w1t[(size_t)NUM_E * FFN * HS];      // w1^T [E][FFN][HS] fp16
__device__ __half g_w2t[(size_t)NUM_E * HS * FFN];      // w2^T [E][HS][FFN] fp16
__device__ __half g_h[(size_t)NUM_E * CAP * FFN];       // gelu(h) fp16
__device__ __half g_out[(size_t)KSPLIT * NUM_E * CAP * HS];  // fp16 partials

// ---------------------------------------------------------------------------
// PTX helpers (baseline PTX only — valid at compute_103 target)
// ---------------------------------------------------------------------------
__device__ __forceinline__ uint32_t smem_u32(const void* p) {
    uint32_t a;
    asm("{ .reg .u64 t; cvta.to.shared.u64 t, %1; cvt.u32.u64 %0, t; }" : "=r"(a) : "l"(p));
    return a;
}
__device__ __forceinline__ void cp16(uint32_t dst, const void* src) {
    asm volatile("cp.async.cg.shared.global [%0], [%1], 16;" :: "r"(dst), "l"(src));
}
__device__ __forceinline__ void cp_commit() {
    asm volatile("cp.async.commit_group;" ::: "memory");
}
template <int N>
__device__ __forceinline__ void cp_wait() {
    asm volatile("cp.async.wait_group %0;" :: "n"(N) : "memory");
}
__device__ __forceinline__ void ldsm4(uint32_t* d, uint32_t addr) {
    asm volatile("ldmatrix.sync.aligned.m8n8.x4.shared.b16 {%0,%1,%2,%3}, [%4];"
        : "=r"(d[0]), "=r"(d[1]), "=r"(d[2]), "=r"(d[3]) : "r"(addr));
}
__device__ __forceinline__ void mma_f16(float* d, const uint32_t* a,
                                        uint32_t b0, uint32_t b1) {
    asm volatile("mma.sync.aligned.m16n8k16.row.col.f32.f16.f16.f32 "
        "{%0,%1,%2,%3}, {%4,%5,%6,%7}, {%8,%9}, {%0,%1,%2,%3};"
        : "+f"(d[0]), "+f"(d[1]), "+f"(d[2]), "+f"(d[3])
        : "r"(a[0]), "r"(a[1]), "r"(a[2]), "r"(a[3]), "r"(b0), "r"(b1));
}

// ---------------------------------------------------------------------------
// Kernel 1: routing (stable argsort semantics)
// ---------------------------------------------------------------------------
__global__ void routing_kernel(const int* __restrict__ te)
{
    __shared__ int shist[512][NUM_E];
    const int tid = threadIdx.x;
    const int PER = NK / 512;
    const int start = tid * PER;

    #pragma unroll
    for (int i = 0; i < PER; i++) g_slot_token[start + i] = -1;

    int h[NUM_E];
    #pragma unroll
    for (int e = 0; e < NUM_E; e++) h[e] = 0;
    #pragma unroll 1
    for (int i = 0; i < PER; i++) h[te[start + i]]++;
    #pragma unroll
    for (int e = 0; e < NUM_E; e++) shist[tid][e] = h[e];
    __syncthreads();

    if (tid < NUM_E) {
        int acc = 0;
        #pragma unroll 1
        for (int t = 0; t < 512; t++) { int v = shist[t][tid]; shist[t][tid] = acc; acc += v; }
    }
    __syncthreads();

    int run[NUM_E];
    #pragma unroll
    for (int e = 0; e < NUM_E; e++) run[e] = shist[tid][e];
    #pragma unroll 1
    for (int i = 0; i < PER; i++) {
        int idx = start + i;
        int ex  = te[idx];
        int pos = run[ex]++;
        if (pos < CAP) {
            int slot = ex * CAP + pos;
            g_flat_slot[idx]   = slot;
            g_slot_token[slot] = idx >> 1;
        } else {
            g_flat_slot[idx] = -1;
        }
    }
}

// ---------------------------------------------------------------------------
// Kernel 2: gather x rows, convert fp32 -> fp16 (8 rows/block, MLP prefetch)
// ---------------------------------------------------------------------------
__global__ void gather_kernel(const float* __restrict__ x)
{
    const int base = blockIdx.x * 8;            // 2048 blocks x 8 slots
    const int half = threadIdx.x >> 7;          // 0..1
    const int c    = (threadIdx.x & 127) * 8;   // 128 thr x 8 cols = 1024

    int toks[8];
    #pragma unroll
    for (int r = 0; r < 8; r++) toks[r] = g_slot_token[base + r];

    #pragma unroll
    for (int rr = 0; rr < 4; rr++) {
        int r   = rr * 2 + half;
        int tok = toks[r];
        __half v[8];
        if (tok >= 0) {
            const float* src = x + (size_t)tok * HS + c;
            #pragma unroll
            for (int i = 0; i < 8; i++) v[i] = __float2half_rn(src[i]);
        } else {
            #pragma unroll
            for (int i = 0; i < 8; i++) v[i] = __float2half_rn(0.f);
        }
        *(uint4*)&g_xg[(size_t)(base + r) * HS + c] = *(uint4*)v;
    }
}

// ---------------------------------------------------------------------------
// Kernel 3: transpose + convert weights. src [E][K][N] fp32 -> dst [E][N][K] fp16
// 64(k) x 64(n) tiles, 256 threads; float2 loads, half2 stores.
// ---------------------------------------------------------------------------
__global__ void wtrans_kernel(const float* __restrict__ w,
                              __half* __restrict__ dst,
                              int K, int N)
{
    __shared__ float t[64][65];
    const int e     = blockIdx.z;
    const int nbase = blockIdx.x * 64;
    const int kbase = blockIdx.y * 64;
    const int tid   = threadIdx.x;

    const float* src = w + (size_t)e * K * N;
    const int cx = (tid & 31) * 2;     // col pair within 64
    #pragma unroll
    for (int i = 0; i < 8; i++) {
        int k = (tid >> 5) + i * 8;
        float2 v = *(const float2*)&src[(size_t)(kbase + k) * N + nbase + cx];
        t[k][cx]     = v.x;
        t[k][cx + 1] = v.y;
    }
    __syncthreads();

    #pragma unroll
    for (int i = 0; i < 8; i++) {
        int idx = tid + i * 256;
        int n   = idx >> 5;            // 0..63
        int p   = idx & 31;            // k-pair 0..31
        __half2 v;
        v.x = __float2half_rn(t[2 * p][n]);
        v.y = __float2half_rn(t[2 * p + 1][n]);
        size_t off = (size_t)e * N * K + (size_t)(nbase + n) * K + kbase + 2 * p;
        *(__half2*)&dst[off] = v;
    }
}

// ---------------------------------------------------------------------------
// GeLU (tanh approximation, matches jax.nn.gelu default)
// ---------------------------------------------------------------------------
__device__ __forceinline__ float gelu_tanh(float x)
{
    float x3 = x * x * x;
    return 0.5f * x * (1.0f + tanhf(0.7978845608028654f * (x + 0.044715f * x3)));
}

// ---------------------------------------------------------------------------
// HMMA GEMM: 128x128x32 CTA tile, 4 warps (2m x 2n of 64x64), 5-stage cp.async,
// 128 threads, 2 CTAs/SM. fp16 operands, fp32 accum, fp16 outputs.
// ZS-way K-split: blockIdx.z = e*ZS + sp.
// SMEM: 5 stages x 20 KB = 100 KB/CTA; 200 KB/SM at 2 CTAs (<= 228 KB).
// ---------------------------------------------------------------------------
#define BKQ         32
#define ROWPITCH    40
#define PART_BYTES  (128 * ROWPITCH * 2)    // 10240
#define STAGE_BYTES (2 * PART_BYTES)        // 20480
#define STAGES      5
#define SMEM_TOTAL  (STAGES * STAGE_BYTES)  // 102400

template <bool GELU, int ZS>
__global__ __launch_bounds__(128, 2)
void moe_gemm_mma(int K, int N)          // K = per-split depth
{
    extern __shared__ char smem[];
    const uint32_t sbase = smem_u32(smem);

    const __half* __restrict__ A = GELU ? g_xg  : g_h;
    const __half* __restrict__ B = GELU ? g_w1t : g_w2t;

    const int tid = threadIdx.x;
    const int wid = tid >> 5;
    const int lid = tid & 31;
    const int wm  = wid >> 1;        // 0..1 -> m offset wm*64
    const int wn  = wid & 1;         // 0..1 -> n offset wn*64

    const int zz = blockIdx.z;
    const int e  = zz / ZS;
    const int sp = zz % ZS;
    const int Kfull = K * ZS;
    const int koff  = sp * K;

    const int m0 = blockIdx.y * 128;
    const int n0 = blockIdx.x * 128;

    const size_t arow0 = (size_t)e * CAP + m0;
    const size_t brow0 = (size_t)e * N + n0;

    const int niter = K / BKQ;

    // ---- stage loader: 2 parts x 512 x 16B chunks, 4 per thread per part ----
    auto load_stage = [&](int s, int k0) {
        uint32_t sb = sbase + s * STAGE_BYTES;
        #pragma unroll
        for (int t = 0; t < 4; t++) {
            int j   = tid + t * 128;          // 0..511
            int row = j >> 2;                 // 0..127
            int c   = j & 3;                  // 16B chunk within 64B row
            uint32_t so = (uint32_t)(row * (ROWPITCH * 2) + c * 16);
            cp16(sb + 0 * PART_BYTES + so, A + (arow0 + row) * Kfull + koff + k0 + c * 8);
            cp16(sb + 1 * PART_BYTES + so, B + (brow0 + row) * Kfull + koff + k0 + c * 8);
        }
        cp_commit();
    };

    // prologue: STAGES-1 stages in flight
    load_stage(0, 0);
    load_stage(1, BKQ);
    load_stage(2, 2 * BKQ);
    load_stage(3, 3 * BKQ);

    float acc[4][8][4];
    #pragma unroll
    for (int i = 0; i < 4; i++)
        #pragma unroll
        for (int j = 0; j < 8; j++)
            #pragma unroll
            for (int q = 0; q < 4; q++) acc[i][j][q] = 0.0f;

    const int g = lid >> 3;     // ldmatrix group 0..3
    const int r = lid & 7;

    int s_cur = 0, s_nxt = STAGES - 1;

    #pragma unroll 1
    for (int i = 0; i < niter; i++) {
        cp_wait<STAGES - 2>();
        __syncthreads();
        if (i + STAGES - 1 < niter) load_stage(s_nxt, (i + STAGES - 1) * BKQ);
        else                        cp_commit();   // keep drain invariant exact

        uint32_t sb = sbase + s_cur * STAGE_BYTES;
        if (++s_cur == STAGES) s_cur = 0;
        if (++s_nxt == STAGES) s_nxt = 0;

        #pragma unroll
        for (int ks = 0; ks < 2; ks++) {
            uint32_t ah[4][4], bh[4][4];
            // A frags: groups map (m + 8*(g&1), k + 8*(g>>1))
            #pragma unroll
            for (int mf = 0; mf < 4; mf++) {
                uint32_t off = (uint32_t)(
                    (wm * 64 + mf * 16 + (g & 1) * 8 + r) * ROWPITCH
                    + ks * 16 + (g >> 1) * 8) * 2;
                ldsm4(ah[mf], sb + off);
            }
            // B frags: groups map (n + 8*(g>>1), k + 8*(g&1)); x4 = 2 n8-frags
            #pragma unroll
            for (int p = 0; p < 4; p++) {
                uint32_t off = (uint32_t)(
                    (wn * 64 + p * 16 + (g >> 1) * 8 + r) * ROWPITCH
                    + ks * 16 + (g & 1) * 8) * 2;
                ldsm4(bh[p], sb + PART_BYTES + off);
            }
            #pragma unroll
            for (int mf = 0; mf < 4; mf++) {
                #pragma unroll
                for (int nf = 0; nf < 8; nf++) {
                    mma_f16(acc[mf][nf], ah[mf],
                            bh[nf >> 1][(nf & 1) * 2],
                            bh[nf >> 1][(nf & 1) * 2 + 1]);
                }
            }
        }
    }
    cp_wait<0>();
    __syncthreads();

    // ---- epilogue: stage accumulators through SMEM (reuse pipeline bufs) ----
    // float[128][132] = 67584 B <= 102400 B
    float (*sh)[132] = (float (*)[132])smem;
    #pragma unroll
    for (int mf = 0; mf < 4; mf++) {
        #pragma unroll
        for (int nf = 0; nf < 8; nf++) {
            int row = wm * 64 + mf * 16 + (lid >> 2);
            int col = wn * 64 + nf * 8 + (lid & 3) * 2;
            *(float2*)&sh[row][col]     = make_float2(acc[mf][nf][0], acc[mf][nf][1]);
            *(float2*)&sh[row + 8][col] = make_float2(acc[mf][nf][2], acc[mf][nf][3]);
        }
    }
    __syncthreads();

    // 128 rows x 64 col-pairs -> fp16x2 stores (coalesced 4B)
    __half* outp = GELU ? g_h : (g_out + (size_t)sp * NUM_E * CAP * HS);
    #pragma unroll 1
    for (int t = 0; t < 64; t++) {
        int idx = tid + t * 128;
        int row = idx >> 6;
        int col = (idx & 63) * 2;
        float f0 = sh[row][col];
        float f1 = sh[row][col + 1];
        if (GELU) { f0 = gelu_tanh(f0); f1 = gelu_tanh(f1); }
        __half2 v;
        v.x = __float2half_rn(f0);
        v.y = __float2half_rn(f1);
        *(__half2*)&outp[(arow0 + row) * N + n0 + col] = v;
    }
}

// ---------------------------------------------------------------------------
// Kernel: combine (sums KSPLIT fp16 partials per slot)
// ---------------------------------------------------------------------------
__global__ void combine_kernel(const float* __restrict__ ew,
                               const float* __restrict__ bias,
                               float* __restrict__ y)
{
    const int t = blockIdx.x;
    const int c = threadIdx.x * 4;

    float4 acc = *(const float4*)&bias[c];
    #pragma unroll
    for (int k = 0; k < TOPK; k++) {
        int slot = g_flat_slot[t * TOPK + k];
        if (slot >= 0) {
            float w = ew[t * TOPK + k];
            #pragma unroll
            for (int s = 0; s < KSPLIT; s++) {
                const __half* p = g_out + (size_t)s * NUM_E * CAP * HS;
                __half2 v01 = *(const __half2*)&p[(size_t)slot * HS + c];
                __half2 v23 = *(const __half2*)&p[(size_t)slot * HS + c + 2];
                acc.x += __half2float(v01.x) * w;
                acc.y += __half2float(v01.y) * w;
                acc.z += __half2float(v23.x) * w;
                acc.w += __half2float(v23.y) * w;
            }
        }
    }
    *(float4*)&y[(size_t)t * HS + c] = acc;
}

// ---------------------------------------------------------------------------
// Entry point.  Fork-join (R13): weight transposes on side stream overlapped
// with routing/gather; GEMM1 waits w1t, GEMM2 waits w2t.
// ---------------------------------------------------------------------------
extern "C" void kernel_launch(void* const* d_in, const int* in_sizes, int n_in,
                              void* d_out, int out_size)
{
    const float* x    = (const float*)d_in[0];
    const float* ew   = (const float*)d_in[1];
    const float* w1   = (const float*)d_in[2];
    const float* w2   = (const float*)d_in[3];
    const float* bias = (const float*)d_in[4];
    const int*   te   = (const int*)d_in[5];
    float*       y    = (float*)d_out;

    static cudaStream_t sW = nullptr;
    static cudaEvent_t  evFork = nullptr, evW1 = nullptr, evW2 = nullptr;
    if (sW == nullptr) {
        cudaStreamCreateWithFlags(&sW, cudaStreamNonBlocking);
        cudaEventCreateWithFlags(&evFork, cudaEventDisableTiming);
        cudaEventCreateWithFlags(&evW1,   cudaEventDisableTiming);
        cudaEventCreateWithFlags(&evW2,   cudaEventDisableTiming);
        cudaFuncSetAttribute((const void*)moe_gemm_mma<true, 1>,
                             cudaFuncAttributeMaxDynamicSharedMemorySize, SMEM_TOTAL);
        cudaFuncSetAttribute((const void*)moe_gemm_mma<false, KSPLIT>,
                             cudaFuncAttributeMaxDynamicSharedMemorySize, SMEM_TOTAL);
    }

    __half *w1t, *w2t;
    cudaGetSymbolAddress((void**)&w1t, g_w1t);
    cudaGetSymbolAddress((void**)&w2t, g_w2t);

    // ---- fork: side stream joins capture via event ----
    cudaEventRecord(evFork, 0);
    cudaStreamWaitEvent(sW, evFork, 0);

    // side stream: weight transposes (independent of routing)
    {
        dim3 g1(FFN / 64, HS / 64, NUM_E);
        wtrans_kernel<<<g1, 256, 0, sW>>>(w1, w1t, HS, FFN);
        cudaEventRecord(evW1, sW);
        dim3 g2(HS / 64, FFN / 64, NUM_E);
        wtrans_kernel<<<g2, 256, 0, sW>>>(w2, w2t, FFN, HS);
        cudaEventRecord(evW2, sW);
    }

    // main stream: routing -> gather
    routing_kernel<<<1, 512>>>(te);
    gather_kernel<<<NUM_E * CAP / 8, 256>>>(x);

    // GEMM1 + GeLU (needs g_xg + w1t)
    cudaStreamWaitEvent(0, evW1, 0);
    {
        dim3 grid(FFN / 128, CAP / 128, NUM_E);
        moe_gemm_mma<true, 1><<<grid, 128, SMEM_TOTAL>>>(HS, FFN);
    }

    // GEMM2, K-split x2 (needs g_h + w2t)
    cudaStreamWaitEvent(0, evW2, 0);
    {
        dim3 grid(HS / 128, CAP / 128, NUM_E * KSPLIT);
        moe_gemm_mma<false, KSPLIT><<<grid, 128, SMEM_TOTAL>>>(FFN / KSPLIT, HS);
    }

    // combine (sums the 2 fp16 partials)
    combine_kernel<<<T_TOK, 256>>>(ew, bias, y);
}

// round 17
// speedup vs baseline: 1.0639x; 1.0639x over previous
#include <cuda_runtime.h>
#include <cuda_fp16.h>
#include <math.h>
#include <stdint.h>

// ---------------------------------------------------------------------------
// Problem constants
// ---------------------------------------------------------------------------
#define NUM_E   8
#define TOPK    2
#define T_TOK   8192
#define NK      (T_TOK * TOPK)
#define HS      1024
#define FFN     4096
#define CAP     2048
#define KSPLIT  2                       // GEMM2 K-split factor

// ---------------------------------------------------------------------------
// Device scratch
// ---------------------------------------------------------------------------
__device__ int    g_flat_slot[NK];
__device__ int    g_slot_token[NUM_E * CAP];
__device__ __half g_xg[(size_t)NUM_E * CAP * HS];       // gathered x, fp16
__device__ __half g_w1f[(size_t)NUM_E * HS * FFN];      // w1 native [E][HS][FFN] fp16
__device__ __half g_w2f[(size_t)NUM_E * FFN * HS];      // w2 native [E][FFN][HS] fp16
__device__ __half g_h[(size_t)NUM_E * CAP * FFN];       // gelu(h) fp16
__device__ float  g_out[(size_t)KSPLIT * NUM_E * CAP * HS];  // fp32 partials

// ---------------------------------------------------------------------------
// PTX helpers (baseline PTX only — valid at compute_103 target)
// ---------------------------------------------------------------------------
__device__ __forceinline__ uint32_t smem_u32(const void* p) {
    uint32_t a;
    asm("{ .reg .u64 t; cvta.to.shared.u64 t, %1; cvt.u32.u64 %0, t; }" : "=r"(a) : "l"(p));
    return a;
}
__device__ __forceinline__ void cp16(uint32_t dst, const void* src) {
    asm volatile("cp.async.cg.shared.global [%0], [%1], 16;" :: "r"(dst), "l"(src));
}
__device__ __forceinline__ void cp_commit() {
    asm volatile("cp.async.commit_group;" ::: "memory");
}
template <int N>
__device__ __forceinline__ void cp_wait() {
    asm volatile("cp.async.wait_group %0;" :: "n"(N) : "memory");
}
__device__ __forceinline__ void ldsm4(uint32_t* d, uint32_t addr) {
    asm volatile("ldmatrix.sync.aligned.m8n8.x4.shared.b16 {%0,%1,%2,%3}, [%4];"
        : "=r"(d[0]), "=r"(d[1]), "=r"(d[2]), "=r"(d[3]) : "r"(addr));
}
__device__ __forceinline__ void ldsm4_t(uint32_t* d, uint32_t addr) {
    asm volatile("ldmatrix.sync.aligned.m8n8.x4.trans.shared.b16 {%0,%1,%2,%3}, [%4];"
        : "=r"(d[0]), "=r"(d[1]), "=r"(d[2]), "=r"(d[3]) : "r"(addr));
}
__device__ __forceinline__ void mma_f16(float* d, const uint32_t* a,
                                        uint32_t b0, uint32_t b1) {
    asm volatile("mma.sync.aligned.m16n8k16.row.col.f32.f16.f16.f32 "
        "{%0,%1,%2,%3}, {%4,%5,%6,%7}, {%8,%9}, {%0,%1,%2,%3};"
        : "+f"(d[0]), "+f"(d[1]), "+f"(d[2]), "+f"(d[3])
        : "r"(a[0]), "r"(a[1]), "r"(a[2]), "r"(a[3]), "r"(b0), "r"(b1));
}

// ---------------------------------------------------------------------------
// Kernel 1: routing (stable argsort semantics)
// ---------------------------------------------------------------------------
__global__ void routing_kernel(const int* __restrict__ te)
{
    __shared__ int shist[512][NUM_E];
    const int tid = threadIdx.x;
    const int PER = NK / 512;
    const int start = tid * PER;

    #pragma unroll
    for (int i = 0; i < PER; i++) g_slot_token[start + i] = -1;

    int h[NUM_E];
    #pragma unroll
    for (int e = 0; e < NUM_E; e++) h[e] = 0;
    #pragma unroll 1
    for (int i = 0; i < PER; i++) h[te[start + i]]++;
    #pragma unroll
    for (int e = 0; e < NUM_E; e++) shist[tid][e] = h[e];
    __syncthreads();

    if (tid < NUM_E) {
        int acc = 0;
        #pragma unroll 1
        for (int t = 0; t < 512; t++) { int v = shist[t][tid]; shist[t][tid] = acc; acc += v; }
    }
    __syncthreads();

    int run[NUM_E];
    #pragma unroll
    for (int e = 0; e < NUM_E; e++) run[e] = shist[tid][e];
    #pragma unroll 1
    for (int i = 0; i < PER; i++) {
        int idx = start + i;
        int ex  = te[idx];
        int pos = run[ex]++;
        if (pos < CAP) {
            int slot = ex * CAP + pos;
            g_flat_slot[idx]   = slot;
            g_slot_token[slot] = idx >> 1;
        } else {
            g_flat_slot[idx] = -1;
        }
    }
}

// ---------------------------------------------------------------------------
// Kernel 2: gather x rows, convert fp32 -> fp16 (8 rows/block, MLP prefetch)
// ---------------------------------------------------------------------------
__global__ void gather_kernel(const float* __restrict__ x)
{
    const int base = blockIdx.x * 8;            // 2048 blocks x 8 slots
    const int half = threadIdx.x >> 7;          // 0..1
    const int c    = (threadIdx.x & 127) * 8;   // 128 thr x 8 cols = 1024

    int toks[8];
    #pragma unroll
    for (int r = 0; r < 8; r++) toks[r] = g_slot_token[base + r];

    #pragma unroll
    for (int rr = 0; rr < 4; rr++) {
        int r   = rr * 2 + half;
        int tok = toks[r];
        __half v[8];
        if (tok >= 0) {
            const float* src = x + (size_t)tok * HS + c;
            #pragma unroll
            for (int i = 0; i < 8; i++) v[i] = __float2half_rn(src[i]);
        } else {
            #pragma unroll
            for (int i = 0; i < 8; i++) v[i] = __float2half_rn(0.f);
        }
        *(uint4*)&g_xg[(size_t)(base + r) * HS + c] = *(uint4*)v;
    }
}

// ---------------------------------------------------------------------------
// Kernel 3: pure streaming fp32 -> fp16 weight conversion (NO transpose —
// the GEMM consumes native [K][N] layout via ldmatrix.trans).
// ---------------------------------------------------------------------------
__global__ void wconv_kernel(const float* __restrict__ w, __half* __restrict__ dst)
{
    size_t i = ((size_t)blockIdx.x * 256 + threadIdx.x) * 8;
    float4 a = *(const float4*)&w[i];
    float4 b = *(const float4*)&w[i + 4];
    __half h[8];
    h[0] = __float2half_rn(a.x); h[1] = __float2half_rn(a.y);
    h[2] = __float2half_rn(a.z); h[3] = __float2half_rn(a.w);
    h[4] = __float2half_rn(b.x); h[5] = __float2half_rn(b.y);
    h[6] = __float2half_rn(b.z); h[7] = __float2half_rn(b.w);
    *(uint4*)&dst[i] = *(uint4*)h;
}

// ---------------------------------------------------------------------------
// GeLU (tanh approximation, matches jax.nn.gelu default)
// ---------------------------------------------------------------------------
__device__ __forceinline__ float gelu_tanh(float x)
{
    float x3 = x * x * x;
    return 0.5f * x * (1.0f + tanhf(0.7978845608028654f * (x + 0.044715f * x3)));
}

// ---------------------------------------------------------------------------
// HMMA GEMM: 128x128x32 CTA tile, 4 warps (2m x 2n of 64x64), 4-stage cp.async,
// 128 threads, 2 CTAs/SM. fp16 operands, fp32 accum.
// A: [E*CAP + m][Kfull] K-major (pitch Kfull), ldmatrix non-trans.
// B: NATIVE [E][Kfull][N] (pitch N), ldmatrix.trans: matrix g loads k-rows
//    [k+(g&1)*8) x n-cols [n+(g>>1)*8) and transposes on delivery -> register
//    layout identical to the old [N][K] non-trans path; MMA mapping unchanged.
// ZS-way K-split: blockIdx.z = e*ZS + sp.
// SMEM stage: A 128 x 80 B (10240) + B 32 k-rows x 272 B (8704) = 18944 B.
// ---------------------------------------------------------------------------
#define BKQ         32
#define ROWPITCH    40                      // A: fp16 elems per smem row (64B+16 pad)
#define A_PART      (128 * ROWPITCH * 2)    // 10240
#define B_PITCH     272                     // B: bytes per k-row (256 data + 16 pad)
#define B_PART      (BKQ * B_PITCH)         // 8704
#define STAGE_BYTES (A_PART + B_PART)       // 18944
#define STAGES      4
#define SMEM_TOTAL  (STAGES * STAGE_BYTES)  // 75776 (>= epilogue 67584)

template <bool GELU, int ZS>
__global__ __launch_bounds__(128, 2)
void moe_gemm_mma(int K, int N)          // K = per-split depth
{
    extern __shared__ char smem[];
    const uint32_t sbase = smem_u32(smem);

    const __half* __restrict__ A = GELU ? g_xg  : g_h;
    const __half* __restrict__ B = GELU ? g_w1f : g_w2f;

    const int tid = threadIdx.x;
    const int wid = tid >> 5;
    const int lid = tid & 31;
    const int wm  = wid >> 1;        // 0..1 -> m offset wm*64
    const int wn  = wid & 1;         // 0..1 -> n offset wn*64

    const int zz = blockIdx.z;
    const int e  = zz / ZS;
    const int sp = zz % ZS;
    const int Kfull = K * ZS;
    const int koff  = sp * K;

    const int m0 = blockIdx.y * 128;
    const int n0 = blockIdx.x * 128;

    const size_t arow0 = (size_t)e * CAP + m0;
    const size_t beoff = (size_t)e * Kfull * N;   // expert base in native B

    const int niter = K / BKQ;

    // ---- stage loader: A 512 chunks (rows=m) + B 512 chunks (rows=k) ----
    auto load_stage = [&](int s, int k0) {
        uint32_t sb = sbase + s * STAGE_BYTES;
        #pragma unroll
        for (int t = 0; t < 4; t++) {
            int j    = tid + t * 128;         // 0..511
            int rowA = j >> 2;                // 0..127 (m)
            int cA   = j & 3;                 // 16B chunk within 64B
            cp16(sb + (uint32_t)(rowA * (ROWPITCH * 2) + cA * 16),
                 A + (arow0 + rowA) * Kfull + koff + k0 + cA * 8);
            int rowB = j >> 4;                // 0..31 (k)
            int cB   = j & 15;                // 16B chunk within 256B row
            cp16(sb + A_PART + (uint32_t)(rowB * B_PITCH + cB * 16),
                 B + beoff + (size_t)(koff + k0 + rowB) * N + n0 + cB * 8);
        }
        cp_commit();
    };

    load_stage(0, 0);
    load_stage(1, BKQ);
    load_stage(2, 2 * BKQ);

    float acc[4][8][4];
    #pragma unroll
    for (int i = 0; i < 4; i++)
        #pragma unroll
        for (int j = 0; j < 8; j++)
            #pragma unroll
            for (int q = 0; q < 4; q++) acc[i][j][q] = 0.0f;

    const int g = lid >> 3;     // ldmatrix group 0..3
    const int r = lid & 7;

    #pragma unroll 1
    for (int i = 0; i < niter; i++) {
        cp_wait<STAGES - 2>();
        __syncthreads();
        if (i + STAGES - 1 < niter) load_stage((i + STAGES - 1) & 3, (i + STAGES - 1) * BKQ);
        else                        cp_commit();   // keep drain invariant exact

        uint32_t sb = sbase + (i & 3) * STAGE_BYTES;

        #pragma unroll
        for (int ks = 0; ks < 2; ks++) {
            uint32_t ah[4][4], bh[4][4];
            // A frags (non-trans, K-major): (m + 8*(g&1), k + 8*(g>>1))
            #pragma unroll
            for (int mf = 0; mf < 4; mf++) {
                uint32_t off = (uint32_t)(
                    (wm * 64 + mf * 16 + (g & 1) * 8 + r) * ROWPITCH
                    + ks * 16 + (g >> 1) * 8) * 2;
                ldsm4(ah[mf], sb + off);
            }
            // B frags (TRANS, native [k][n]): row = k + (g&1)*8 + r,
            // col = n + (g>>1)*8; .trans restores the [N][K] register layout.
            #pragma unroll
            for (int p = 0; p < 4; p++) {
                uint32_t off = (uint32_t)(
                    (ks * 16 + (g & 1) * 8 + r) * B_PITCH
                    + (wn * 64 + p * 16 + (g >> 1) * 8) * 2);
                ldsm4_t(bh[p], sb + A_PART + off);
            }
            #pragma unroll
            for (int mf = 0; mf < 4; mf++) {
                #pragma unroll
                for (int nf = 0; nf < 8; nf++) {
                    mma_f16(acc[mf][nf], ah[mf],
                            bh[nf >> 1][(nf & 1) * 2],
                            bh[nf >> 1][(nf & 1) * 2 + 1]);
                }
            }
        }
    }
    cp_wait<0>();
    __syncthreads();

    // ---- epilogue: stage accumulators through SMEM (reuse pipeline bufs) ----
    // float[128][132] = 67584 B <= SMEM_TOTAL
    float (*sh)[132] = (float (*)[132])smem;
    #pragma unroll
    for (int mf = 0; mf < 4; mf++) {
        #pragma unroll
        for (int nf = 0; nf < 8; nf++) {
            int row = wm * 64 + mf * 16 + (lid >> 2);
            int col = wn * 64 + nf * 8 + (lid & 3) * 2;
            *(float2*)&sh[row][col]     = make_float2(acc[mf][nf][0], acc[mf][nf][1]);
            *(float2*)&sh[row + 8][col] = make_float2(acc[mf][nf][2], acc[mf][nf][3]);
        }
    }
    __syncthreads();

    if (GELU) {
        // 128 rows x 64 col-pairs -> fp16x2 stores (coalesced 4B)
        #pragma unroll 1
        for (int t = 0; t < 64; t++) {
            int idx = tid + t * 128;
            int row = idx >> 6;
            int col = (idx & 63) * 2;
            __half2 v;
            v.x = __float2half_rn(gelu_tanh(sh[row][col]));
            v.y = __float2half_rn(gelu_tanh(sh[row][col + 1]));
            *(__half2*)&g_h[(arow0 + row) * N + n0 + col] = v;
        }
    } else {
        // 128 rows x 32 float4, coalesced, into this split's partial buffer
        float* outp = g_out + (size_t)sp * NUM_E * CAP * HS;
        #pragma unroll 1
        for (int t = 0; t < 32; t++) {
            int idx = tid + t * 128;
            int row = idx >> 5;
            int col = (idx & 31) * 4;
            float4 v = *(float4*)&sh[row][col];
            *(float4*)&outp[(arow0 + row) * N + n0 + col] = v;
        }
    }
}

// ---------------------------------------------------------------------------
// Kernel: combine (sums KSPLIT fp32 partials per slot)
// ---------------------------------------------------------------------------
__global__ void combine_kernel(const float* __restrict__ ew,
                               const float* __restrict__ bias,
                               float* __restrict__ y)
{
    const int t = blockIdx.x;
    const int c = threadIdx.x * 4;

    float4 acc = *(const float4*)&bias[c];
    #pragma unroll
    for (int k = 0; k < TOPK; k++) {
        int slot = g_flat_slot[t * TOPK + k];
        if (slot >= 0) {
            float w = ew[t * TOPK + k];
            #pragma unroll
            for (int s = 0; s < KSPLIT; s++) {
                const float* p = g_out + (size_t)s * NUM_E * CAP * HS;
                float4 v = *(const float4*)&p[(size_t)slot * HS + c];
                acc.x += v.x * w; acc.y += v.y * w;
                acc.z += v.z * w; acc.w += v.w * w;
            }
        }
    }
    *(float4*)&y[(size_t)t * HS + c] = acc;
}

// ---------------------------------------------------------------------------
// Entry point.  Fork-join: streaming weight conversions on a side stream
// overlapped with routing/gather; GEMM1 waits w1f, GEMM2 waits w2f.
// ---------------------------------------------------------------------------
extern "C" void kernel_launch(void* const* d_in, const int* in_sizes, int n_in,
                              void* d_out, int out_size)
{
    const float* x    = (const float*)d_in[0];
    const float* ew   = (const float*)d_in[1];
    const float* w1   = (const float*)d_in[2];
    const float* w2   = (const float*)d_in[3];
    const float* bias = (const float*)d_in[4];
    const int*   te   = (const int*)d_in[5];
    float*       y    = (float*)d_out;

    static cudaStream_t sW = nullptr;
    static cudaEvent_t  evFork = nullptr, evW1 = nullptr, evW2 = nullptr;
    if (sW == nullptr) {
        cudaStreamCreateWithFlags(&sW, cudaStreamNonBlocking);
        cudaEventCreateWithFlags(&evFork, cudaEventDisableTiming);
        cudaEventCreateWithFlags(&evW1,   cudaEventDisableTiming);
        cudaEventCreateWithFlags(&evW2,   cudaEventDisableTiming);
        cudaFuncSetAttribute((const void*)moe_gemm_mma<true, 1>,
                             cudaFuncAttributeMaxDynamicSharedMemorySize, SMEM_TOTAL);
        cudaFuncSetAttribute((const void*)moe_gemm_mma<false, KSPLIT>,
                             cudaFuncAttributeMaxDynamicSharedMemorySize, SMEM_TOTAL);
    }

    __half *w1f, *w2f;
    cudaGetSymbolAddress((void**)&w1f, g_w1f);
    cudaGetSymbolAddress((void**)&w2f, g_w2f);

    // ---- fork: side stream joins capture via event ----
    cudaEventRecord(evFork, 0);
    cudaStreamWaitEvent(sW, evFork, 0);

    // side stream: streaming weight conversions (independent of routing)
    {
        const int grid = (int)((size_t)NUM_E * HS * FFN / 2048);   // 16384
        wconv_kernel<<<grid, 256, 0, sW>>>(w1, w1f);
        cudaEventRecord(evW1, sW);
        wconv_kernel<<<grid, 256, 0, sW>>>(w2, w2f);
        cudaEventRecord(evW2, sW);
    }

    // main stream: routing -> gather
    routing_kernel<<<1, 512>>>(te);
    gather_kernel<<<NUM_E * CAP / 8, 256>>>(x);

    // GEMM1 + GeLU (needs g_xg + w1f)
    cudaStreamWaitEvent(0, evW1, 0);
    {
        dim3 grid(FFN / 128, CAP / 128, NUM_E);
        moe_gemm_mma<true, 1><<<grid, 128, SMEM_TOTAL>>>(HS, FFN);
    }

    // GEMM2, K-split x2 (needs g_h + w2f)
    cudaStreamWaitEvent(0, evW2, 0);
    {
        dim3 grid(HS / 128, CAP / 128, NUM_E * KSPLIT);
        moe_gemm_mma<false, KSPLIT><<<grid, 128, SMEM_TOTAL>>>(FFN / KSPLIT, HS);
    }

    // combine (sums the 2 fp32 partials)
    combine_kernel<<<T_TOK, 256>>>(ew, bias, y);
}